// round 14
// baseline (speedup 1.0000x reference)
#include <cuda_runtime.h>
#include <math.h>

#define DIM 64
#define FIN 32
#define MAXN 50048
#define MAXE 60032
#define MAXB 256
#define ELLW 16
#define CAP 320
#define FS 65

#define AST 68      // activation stride (dim-major [64][64 nodes + pad]); mult of 4
#define WAST 68     // stage A weight stride
#define WGST 388    // gate weight stride: 16 groups * 24 + pad (16B-aligned rows)

typedef unsigned long long ull;

// ---------------- device scratch ----------------
__device__ float g_ew[DIM * DIM];
__device__ float g_feat2[MAXN * DIM];
__device__ int   g_deg[MAXN];
__device__ int   g_ell[MAXN * ELLW];
__device__ float g_e[MAXN];
__device__ int   g_gstart[MAXB + 1];
__device__ int   g_ctr[4];          // work-stealing counters (one per k_iter launch)

__device__ __forceinline__ float fsig(float x) {
    return __fdividef(1.0f, 1.0f + __expf(-x));
}
__device__ __forceinline__ float ftanh(float x) {
    float e = __expf(2.0f * x);
    return __fdividef(e - 1.0f, e + 1.0f);
}
__device__ __forceinline__ ull ffma2(ull a, ull b, ull c) {
    ull d;
    asm("fma.rn.f32x2 %0, %1, %2, %3;" : "=l"(d) : "l"(a), "l"(b), "l"(c));
    return d;
}
__device__ __forceinline__ ull pack2(float x) {
    ull r;
    asm("mov.b64 %0, {%1, %1};" : "=l"(r) : "r"(__float_as_uint(x)));
    return r;
}
__device__ __forceinline__ float2 unpack2(ull v) {
    float2 f;
    asm("mov.b64 {%0, %1}, %2;" : "=f"(f.x), "=f"(f.y) : "l"(v));
    return f;
}

// ============ launch 0: EW + zero deg + init gstart + zero steal counters ============
__global__ void k_init(const float* __restrict__ nn1_w, const float* __restrict__ nn1_b,
                       const float* __restrict__ nn2_w, const float* __restrict__ nn2_b,
                       int N, int B) {
    int i = blockIdx.x * blockDim.x + threadIdx.x;
    if (i < DIM * DIM) {
        float acc = nn2_b[i];
        const float* row = &nn2_w[i * DIM];
#pragma unroll 8
        for (int dd = 0; dd < DIM; dd++)
            acc += fmaxf(nn1_w[dd] + nn1_b[dd], 0.0f) * row[dd];
        g_ew[i] = acc;
    }
    if (i < N) g_deg[i] = 0;
    if (i <= B) g_gstart[i] = N;
    if (i < 4) g_ctr[i] = 0;
}

// ============ launch 1: ELL insert + mark graph starts ============
__global__ void k_count(const int* __restrict__ src, const int* __restrict__ dst,
                        const int* __restrict__ batch, int E, int N) {
    int i = blockIdx.x * blockDim.x + threadIdx.x;
    if (i < E) {
        int dn = dst[i];
        int slot = atomicAdd(&g_deg[dn], 1);
        if (slot < ELLW) g_ell[dn * ELLW + slot] = src[i];
    }
    if (i < N) {
        if (i == 0 || batch[i - 1] != batch[i]) atomicMin(&g_gstart[batch[i]], i);
    }
}

// ============ launch 2: lin0 (+ gstart monotone fix in block 0) ============
__global__ void k_lin0(const float* __restrict__ x, const float* __restrict__ w,
                       const float* __restrict__ b, float* __restrict__ feat, int N, int B) {
    __shared__ float sw[DIM * 33];
    __shared__ float sb[DIM];
    __shared__ float sx[16 * FIN];
    int t = threadIdx.x;
    if (blockIdx.x == 0 && t == 0) {
        g_gstart[B] = N;
        for (int bb = B - 1; bb >= 0; bb--)
            if (g_gstart[bb] > g_gstart[bb + 1]) g_gstart[bb] = g_gstart[bb + 1];
    }
    for (int i = t; i < DIM * FIN; i += 256) sw[(i >> 5) * 33 + (i & 31)] = w[i];
    if (t < DIM) sb[t] = b[t];
    __syncthreads();
    int d = t & 63, tq = t >> 6;
    for (int tile = blockIdx.x * 16; tile < N; tile += gridDim.x * 16) {
        for (int i = t; i < 16 * FIN; i += 256) {
            int n = tile + (i >> 5);
            sx[i] = (n < N) ? x[n * FIN + (i & 31)] : 0.0f;
        }
        __syncthreads();
#pragma unroll
        for (int k = 0; k < 4; k++) {
            int loc = tq * 4 + k;
            int n = tile + loc;
            if (n < N) {
                float acc = sb[d];
                const float* xr = &sx[loc * FIN];
#pragma unroll
                for (int f = 0; f < FIN; f++) acc += xr[f] * sw[d * 33 + f];
                feat[n * DIM + d] = fmaxf(acc, 0.0f);
            }
        }
        __syncthreads();
    }
}

// ============ fused gather + NNConv + GRU: FFMA2 node-pair lanes, work-stealing tiles ============
// smem (floats)
#define OFF_WA 0                               // [64 k][WAST] EW k-major scalar
#define OFF_WG (64 * WAST)                     // 4352: [64 k][WGST]: grp*24 + pass*12 + g*4 + dd
#define OFF_S  (OFF_WG + 64 * WGST)            // 29184: 2 x [64 k][AST]
#define OFF_H  (OFF_S + 2 * 64 * AST)          // 37888: 2 x [64 k][AST]
#define OFF_M  (OFF_H + 2 * 64 * AST)          // 46592: [64 d][AST]
#define OFF_CB (OFF_M + 64 * AST)              // 50944
#define OFF_B4 (OFF_CB + 64)                   // 51008: bR | bZ | bNi | bNh
#define SMEM_ITER_FLOATS (OFF_B4 + 256)        // 51264 floats = 200.25 KB

__device__ __forceinline__ void gather8(const float* __restrict__ fin, int tile, int q8,
                                        int col, int N, float* sv, float* hv) {
#pragma unroll
    for (int j = 0; j < 8; j++) {
        int n = tile + q8 + j;
        float s = 0.0f, h = 0.0f;
        if (n < N) {
            h = fin[n * DIM + col];
            int dgc = g_deg[n]; if (dgc > ELLW) dgc = ELLW;
            const int* er = &g_ell[n * ELLW];
            for (int e = 0; e < dgc; e++) s += fin[er[e] * DIM + col];
            s *= (dgc > 0) ? __fdividef(1.0f, (float)dgc) : 0.0f;
        }
        sv[j] = s; hv[j] = h;
    }
}

__global__ void __launch_bounds__(512, 1)
k_iter(const float* __restrict__ fin, float* __restrict__ fout,
       const float* __restrict__ wih, const float* __restrict__ whh,
       const float* __restrict__ bih, const float* __restrict__ bhh,
       const float* __restrict__ convb, int N, int ci) {
    extern __shared__ float sm[];
    float* sWa = sm + OFF_WA;
    float* sWG = sm + OFF_WG;
    float* sS  = sm + OFF_S;
    float* sH  = sm + OFF_H;
    float* sM  = sm + OFF_M;
    float* sCb = sm + OFF_CB;
    float* sB4 = sm + OFF_B4;
    __shared__ int s_tile;

    int t = threadIdx.x;
    // EW k-major scalar
    for (int i = t; i < DIM * DIM; i += 512) {
        int k = i >> 6, d = i & 63;
        sWa[k * WAST + d] = g_ew[i];
    }
    // gate weights: [k][grp*24 + pass*12 + g*4 + dd]
    for (int i = t; i < 3 * DIM * DIM; i += 512) {
        int r = i >> 6, k = i & 63;        // r = gate*64 + d_out
        int g = r >> 6, d = r & 63;
        int grp = d >> 2, dd = d & 3;
        sWG[k * WGST + grp * 24 + g * 4 + dd]      = wih[i];
        sWG[k * WGST + grp * 24 + 12 + g * 4 + dd] = whh[i];
    }
    if (t < 64) {
        sCb[t] = convb[t];
        sB4[t]       = bih[t] + bhh[t];             // r bias combined
        sB4[64 + t]  = bih[64 + t] + bhh[64 + t];   // z bias combined
        sB4[128 + t] = bih[128 + t];                // n input bias
        sB4[192 + t] = bhh[128 + t];                // n hidden bias
    }
    if (t == 0) s_tile = atomicAdd(&g_ctr[ci], 1) * 64;   // initial steal
    __syncthreads();

    int w = t >> 5, ln = t & 31;          // 16 warps; warp w = dims 4w..4w+3; lane = node-pair 2ln
    int col = t & 63, q8 = (t >> 6) * 8;  // gather mapping
    int d0 = 4 * w;

    int tile = s_tile;
    float sv[8], hv[8];
    if (tile < N) gather8(fin, tile, q8, col, N, sv, hv);

    int buf = 0;
    while (tile < N) {
        float* Sb = sS + buf * (64 * AST);
        float* Hb = sH + buf * (64 * AST);

        // ---- commit prefetched gather
        *(float4*)&Sb[col * AST + q8]     = make_float4(sv[0], sv[1], sv[2], sv[3]);
        *(float4*)&Sb[col * AST + q8 + 4] = make_float4(sv[4], sv[5], sv[6], sv[7]);
        *(float4*)&Hb[col * AST + q8]     = make_float4(hv[0], hv[1], hv[2], hv[3]);
        *(float4*)&Hb[col * AST + q8 + 4] = make_float4(hv[4], hv[5], hv[6], hv[7]);
        if (t == 0) s_tile = atomicAdd(&g_ctr[ci], 1) * 64;   // steal next tile
        __syncthreads();   // B1: publishes gather commit + s_tile

        // ---- prefetch next tile's gather (overlaps compute)
        int nxt = s_tile;
        if (nxt < N) gather8(fin, nxt, q8, col, N, sv, hv);

        // ---- stage A: m = relu(s @ EW + cb); FFMA2 node-pairs, warp = 4 dims x 64 nodes
        {
            ull a0 = 0, a1 = 0, a2 = 0, a3 = 0;
            const float* Sp = &Sb[2 * ln];
            const float* Wp = &sWa[d0];
#pragma unroll 4
            for (int k = 0; k < 64; k++) {
                ull s2 = *(const ull*)&Sp[k * AST];
                float4 w4 = *(const float4*)&Wp[k * WAST];
                a0 = ffma2(s2, pack2(w4.x), a0);
                a1 = ffma2(s2, pack2(w4.y), a1);
                a2 = ffma2(s2, pack2(w4.z), a2);
                a3 = ffma2(s2, pack2(w4.w), a3);
            }
            float2 u;
            u = unpack2(a0);
            *(float2*)&sM[(d0 + 0) * AST + 2 * ln] =
                make_float2(fmaxf(u.x + sCb[d0 + 0], 0.0f), fmaxf(u.y + sCb[d0 + 0], 0.0f));
            u = unpack2(a1);
            *(float2*)&sM[(d0 + 1) * AST + 2 * ln] =
                make_float2(fmaxf(u.x + sCb[d0 + 1], 0.0f), fmaxf(u.y + sCb[d0 + 1], 0.0f));
            u = unpack2(a2);
            *(float2*)&sM[(d0 + 2) * AST + 2 * ln] =
                make_float2(fmaxf(u.x + sCb[d0 + 2], 0.0f), fmaxf(u.y + sCb[d0 + 2], 0.0f));
            u = unpack2(a3);
            *(float2*)&sM[(d0 + 3) * AST + 2 * ln] =
                make_float2(fmaxf(u.x + sCb[d0 + 3], 0.0f), fmaxf(u.y + sCb[d0 + 3], 0.0f));
        }
        __syncthreads();   // B2

        // ---- gates: warp = 4 dims x 64 nodes; pass1 input gates, pass2 folds hidden
        {
            ull ir[4] = {0,0,0,0}, iz[4] = {0,0,0,0}, inn[4] = {0,0,0,0}, hn[4] = {0,0,0,0};
            const float* Wg = &sWG[24 * w];
            const float* Mp = &sM[2 * ln];
            const float* Hp = &Hb[2 * ln];
            // pass 1: gi = m @ Wih^T
#pragma unroll 4
            for (int k = 0; k < 64; k++) {
                ull m2 = *(const ull*)&Mp[k * AST];
                float4 wr4 = *(const float4*)&Wg[k * WGST];
                float4 wz4 = *(const float4*)&Wg[k * WGST + 4];
                float4 wn4 = *(const float4*)&Wg[k * WGST + 8];
                ir[0] = ffma2(m2, pack2(wr4.x), ir[0]);
                ir[1] = ffma2(m2, pack2(wr4.y), ir[1]);
                ir[2] = ffma2(m2, pack2(wr4.z), ir[2]);
                ir[3] = ffma2(m2, pack2(wr4.w), ir[3]);
                iz[0] = ffma2(m2, pack2(wz4.x), iz[0]);
                iz[1] = ffma2(m2, pack2(wz4.y), iz[1]);
                iz[2] = ffma2(m2, pack2(wz4.z), iz[2]);
                iz[3] = ffma2(m2, pack2(wz4.w), iz[3]);
                inn[0] = ffma2(m2, pack2(wn4.x), inn[0]);
                inn[1] = ffma2(m2, pack2(wn4.y), inn[1]);
                inn[2] = ffma2(m2, pack2(wn4.z), inn[2]);
                inn[3] = ffma2(m2, pack2(wn4.w), inn[3]);
            }
            // pass 2: gh = h @ Whh^T; fold r,z into ir,iz; hn separate
#pragma unroll 4
            for (int k = 0; k < 64; k++) {
                ull h2 = *(const ull*)&Hp[k * AST];
                float4 vr4 = *(const float4*)&Wg[k * WGST + 12];
                float4 vz4 = *(const float4*)&Wg[k * WGST + 16];
                float4 vn4 = *(const float4*)&Wg[k * WGST + 20];
                ir[0] = ffma2(h2, pack2(vr4.x), ir[0]);
                ir[1] = ffma2(h2, pack2(vr4.y), ir[1]);
                ir[2] = ffma2(h2, pack2(vr4.z), ir[2]);
                ir[3] = ffma2(h2, pack2(vr4.w), ir[3]);
                iz[0] = ffma2(h2, pack2(vz4.x), iz[0]);
                iz[1] = ffma2(h2, pack2(vz4.y), iz[1]);
                iz[2] = ffma2(h2, pack2(vz4.z), iz[2]);
                iz[3] = ffma2(h2, pack2(vz4.w), iz[3]);
                hn[0] = ffma2(h2, pack2(vn4.x), hn[0]);
                hn[1] = ffma2(h2, pack2(vn4.y), hn[1]);
                hn[2] = ffma2(h2, pack2(vn4.z), hn[2]);
                hn[3] = ffma2(h2, pack2(vn4.w), hn[3]);
            }
            // epilogue: 4 dims x 2 nodes, fully thread-local
            float o0[4], o1[4];
#pragma unroll
            for (int dd = 0; dd < 4; dd++) {
                int d = d0 + dd;
                float2 R  = unpack2(ir[dd]);
                float2 Z  = unpack2(iz[dd]);
                float2 I  = unpack2(inn[dd]);
                float2 Hn = unpack2(hn[dd]);
                float2 h0 = *(const float2*)&Hp[d * AST];
                float bR = sB4[d], bZ = sB4[64 + d], bNi = sB4[128 + d], bNh = sB4[192 + d];
                float r0 = fsig(R.x + bR), r1 = fsig(R.y + bR);
                float z0 = fsig(Z.x + bZ), z1 = fsig(Z.y + bZ);
                float g0 = ftanh(I.x + bNi + r0 * (Hn.x + bNh));
                float g1 = ftanh(I.y + bNi + r1 * (Hn.y + bNh));
                o0[dd] = (1.0f - z0) * g0 + z0 * h0.x;
                o1[dd] = (1.0f - z1) * g1 + z1 * h0.y;
            }
            int n0 = tile + 2 * ln;
            if (n0 < N)
                *(float4*)&fout[n0 * DIM + d0] = make_float4(o0[0], o0[1], o0[2], o0[3]);
            if (n0 + 1 < N)
                *(float4*)&fout[(n0 + 1) * DIM + d0] = make_float4(o1[0], o1[1], o1[2], o1[3]);
        }
        tile = nxt;
        buf ^= 1;
    }
}

// ============ fused Set2Set with smem feature cache ============
#define S2_F 0
#define S2_E (S2_F + CAP * FS)
#define S2_RED (S2_E + CAP)
#define S2_GATE (S2_RED + 256)
#define S2_Q (S2_GATE + 256)
#define S2_HL (S2_Q + 128)
#define S2_CL (S2_HL + 64)
#define SMEM_S2S_FLOATS (S2_CL + 64)

__global__ void __launch_bounds__(256, 1)
k_set2set(const float* __restrict__ feat,
          const float* __restrict__ wih, const float* __restrict__ whh,
          const float* __restrict__ bih, const float* __restrict__ bhh,
          float* __restrict__ out) {
    extern __shared__ float sm[];
    float* sF = sm + S2_F;
    float* sE = sm + S2_E;
    float* sRed = sm + S2_RED;
    float* sGate = sm + S2_GATE;
    float* sQ = sm + S2_Q;
    float* sHl = sm + S2_HL;
    float* sCl = sm + S2_CL;

    int b = blockIdx.x, t = threadIdx.x;
    int s0 = g_gstart[b], s1 = g_gstart[b + 1], cnt = s1 - s0;
    int cc = (cnt < CAP) ? cnt : CAP;
    for (int i = t; i < cc * DIM; i += 256) {
        int j = i >> 6, d = i & 63;
        sF[j * FS + d] = feat[(s0 + j) * DIM + d];
    }
    if (t < 128) sQ[t] = 0.0f;
    if (t < 64) { sHl[t] = 0.0f; sCl[t] = 0.0f; }
    __syncthreads();

    for (int step = 0; step < 3; step++) {
        {
            float acc = bih[t] + bhh[t];
            const float* wr = &wih[t * 2 * DIM];
#pragma unroll
            for (int j = 0; j < 2 * DIM; j += 4) {
                float4 w = *(const float4*)&wr[j];
                float4 q = *(const float4*)&sQ[j];
                acc += w.x * q.x + w.y * q.y + w.z * q.z + w.w * q.w;
            }
            const float* vr = &whh[t * DIM];
#pragma unroll
            for (int j = 0; j < DIM; j += 4) {
                float4 w = *(const float4*)&vr[j];
                float4 h = *(const float4*)&sHl[j];
                acc += w.x * h.x + w.y * h.y + w.z * h.z + w.w * h.w;
            }
            sGate[t] = acc;
        }
        __syncthreads();
        if (t < 64) {
            float ig = fsig(sGate[t]);
            float fg = fsig(sGate[64 + t]);
            float gg = ftanh(sGate[128 + t]);
            float og = fsig(sGate[192 + t]);
            float c = fg * sCl[t] + ig * gg;
            sCl[t] = c;
            sHl[t] = og * ftanh(c);
        }
        __syncthreads();

        float mx = -1e30f;
        for (int j = t; j < cnt; j += 256) {
            float v = 0.0f;
            if (j < CAP) {
                const float* fr = &sF[j * FS];
#pragma unroll 8
                for (int dd = 0; dd < DIM; dd++) v += fr[dd] * sHl[dd];
                sE[j] = v;
            } else {
                const float* fr = &feat[(s0 + j) * DIM];
                for (int dd = 0; dd < DIM; dd++) v += fr[dd] * sHl[dd];
                g_e[s0 + j] = v;
            }
            mx = fmaxf(mx, v);
        }
        sRed[t] = mx;
        __syncthreads();
        for (int off = 128; off > 0; off >>= 1) {
            if (t < off) sRed[t] = fmaxf(sRed[t], sRed[t + off]);
            __syncthreads();
        }
        float emax = (cnt > 0) ? sRed[0] : 0.0f;
        __syncthreads();

        float sme = 0.0f;
        for (int j = t; j < cnt; j += 256) {
            float e = (j < CAP) ? sE[j] : g_e[s0 + j];
            sme += __expf(e - emax);
        }
        sRed[t] = sme;
        __syncthreads();
        for (int off = 128; off > 0; off >>= 1) {
            if (t < off) sRed[t] += sRed[t + off];
            __syncthreads();
        }
        float scale = __fdividef(1.0f, sRed[0] + 1e-16f);
        __syncthreads();
        for (int j = t; j < cnt; j += 256) {
            if (j < CAP) sE[j] = __expf(sE[j] - emax) * scale;
            else g_e[s0 + j] = __expf(g_e[s0 + j] - emax) * scale;
        }
        __syncthreads();

        {
            int d = t & 63, q = t >> 6;
            float acc = 0.0f;
            for (int j = q; j < cnt; j += 4) {
                float a = (j < CAP) ? sE[j] : g_e[s0 + j];
                float fv = (j < CAP) ? sF[j * FS + d] : feat[(s0 + j) * DIM + d];
                acc += a * fv;
            }
            sRed[t] = acc;
        }
        __syncthreads();
        if (t < 64) {
            float r = sRed[t] + sRed[64 + t] + sRed[128 + t] + sRed[192 + t];
            if (step == 2) {
                out[b * 2 * DIM + t] = sHl[t];
                out[b * 2 * DIM + DIM + t] = r;
            } else {
                sQ[t] = sHl[t];
                sQ[DIM + t] = r;
            }
        }
        __syncthreads();
    }
}

// ---------------- launch ----------------
extern "C" void kernel_launch(void* const* d_in, const int* in_sizes, int n_in,
                              void* d_out, int out_size) {
    const float* x        = (const float*)d_in[0];
    const int*   ei       = (const int*)d_in[1];
    const int*   batch    = (const int*)d_in[2];
    const float* lin0_w   = (const float*)d_in[3];
    const float* lin0_b   = (const float*)d_in[4];
    const float* nn1_w    = (const float*)d_in[5];
    const float* nn1_b    = (const float*)d_in[6];
    const float* nn2_w    = (const float*)d_in[7];
    const float* nn2_b    = (const float*)d_in[8];
    const float* conv_b   = (const float*)d_in[9];
    const float* gru_w_ih = (const float*)d_in[10];
    const float* gru_w_hh = (const float*)d_in[11];
    const float* gru_b_ih = (const float*)d_in[12];
    const float* gru_b_hh = (const float*)d_in[13];
    const float* lstm_w_ih = (const float*)d_in[14];
    const float* lstm_w_hh = (const float*)d_in[15];
    const float* lstm_b_ih = (const float*)d_in[16];
    const float* lstm_b_hh = (const float*)d_in[17];

    int N = in_sizes[2];
    int E = in_sizes[1] / 2;
    int B = (out_size - N * DIM) / (2 * DIM);

    float* out  = (float*)d_out;
    float* feat = out + B * 2 * DIM;

    float* feat2 = nullptr;
    cudaGetSymbolAddress((void**)&feat2, g_feat2);

    const int* src = ei;
    const int* dst = ei + E;

    const size_t smem_iter = SMEM_ITER_FLOATS * sizeof(float);
    const size_t smem_s2s  = SMEM_S2S_FLOATS * sizeof(float);
    cudaFuncSetAttribute(k_iter, cudaFuncAttributeMaxDynamicSharedMemorySize, (int)smem_iter);
    cudaFuncSetAttribute(k_set2set, cudaFuncAttributeMaxDynamicSharedMemorySize, (int)smem_s2s);

    int mx1 = (N > DIM * DIM ? N : DIM * DIM);
    int mx2 = (E > N ? E : N);

    // 0: EW + zero deg + gstart init + steal-counter reset
    k_init<<<(mx1 + 1023) / 1024, 1024>>>(nn1_w, nn1_b, nn2_w, nn2_b, N, B);
    // 1: ELL adjacency insert + graph-start marks
    k_count<<<(mx2 + 1023) / 1024, 1024>>>(src, dst, batch, E, N);
    // 2: lin0 (+ gstart fix)
    k_lin0<<<148, 256>>>(x, lin0_w, lin0_b, feat2, N, B);

    // 3..5: fused gather + NNConv + GRU, work-stealing (index 3 gets profiled)
    k_iter<<<148, 512, smem_iter>>>(feat2, feat, gru_w_ih, gru_w_hh, gru_b_ih, gru_b_hh, conv_b, N, 0);
    k_iter<<<148, 512, smem_iter>>>(feat, feat2, gru_w_ih, gru_w_hh, gru_b_ih, gru_b_hh, conv_b, N, 1);
    k_iter<<<148, 512, smem_iter>>>(feat2, feat, gru_w_ih, gru_w_hh, gru_b_ih, gru_b_hh, conv_b, N, 2);

    // 6: fused Set2Set
    k_set2set<<<B, 256, smem_s2s>>>(feat, lstm_w_ih, lstm_w_hh, lstm_b_ih, lstm_b_hh, out);
}

// round 15
// speedup vs baseline: 1.0218x; 1.0218x over previous
#include <cuda_runtime.h>
#include <math.h>

#define DIM 64
#define FIN 32
#define MAXN 50048
#define MAXE 60032
#define MAXB 256
#define ELLW 16
#define CAP 320
#define FS 65

#define TILE 128
#define AST2 132    // activation stride (dim-major [64][128 nodes + pad])
#define WAST 68     // stage A weight stride
#define WGST 388    // gate weight stride: 16 groups * 24 + pad

typedef unsigned long long ull;

// ---------------- device scratch ----------------
__device__ float g_ew[DIM * DIM];
__device__ float g_feat2[MAXN * DIM];
__device__ int   g_deg[MAXN];
__device__ int   g_ell[MAXN * ELLW];
__device__ float g_e[MAXN];
__device__ int   g_gstart[MAXB + 1];
__device__ int   g_ctr[4];

__device__ __forceinline__ float fsig(float x) {
    return __fdividef(1.0f, 1.0f + __expf(-x));
}
__device__ __forceinline__ float ftanh(float x) {
    float e = __expf(2.0f * x);
    return __fdividef(e - 1.0f, e + 1.0f);
}
__device__ __forceinline__ ull ffma2(ull a, ull b, ull c) {
    ull d;
    asm("fma.rn.f32x2 %0, %1, %2, %3;" : "=l"(d) : "l"(a), "l"(b), "l"(c));
    return d;
}
__device__ __forceinline__ ull pack2(float x) {
    ull r;
    asm("mov.b64 %0, {%1, %1};" : "=l"(r) : "r"(__float_as_uint(x)));
    return r;
}
__device__ __forceinline__ float2 unpack2(ull v) {
    float2 f;
    asm("mov.b64 {%0, %1}, %2;" : "=f"(f.x), "=f"(f.y) : "l"(v));
    return f;
}

// ============ launch 0: EW + zero deg + init gstart + zero steal counters ============
__global__ void k_init(const float* __restrict__ nn1_w, const float* __restrict__ nn1_b,
                       const float* __restrict__ nn2_w, const float* __restrict__ nn2_b,
                       int N, int B) {
    int i = blockIdx.x * blockDim.x + threadIdx.x;
    if (i < DIM * DIM) {
        float acc = nn2_b[i];
        const float* row = &nn2_w[i * DIM];
#pragma unroll 8
        for (int dd = 0; dd < DIM; dd++)
            acc += fmaxf(nn1_w[dd] + nn1_b[dd], 0.0f) * row[dd];
        g_ew[i] = acc;
    }
    if (i < N) g_deg[i] = 0;
    if (i <= B) g_gstart[i] = N;
    if (i < 4) g_ctr[i] = 0;
}

// ============ launch 1: ELL insert + mark graph starts ============
__global__ void k_count(const int* __restrict__ src, const int* __restrict__ dst,
                        const int* __restrict__ batch, int E, int N) {
    int i = blockIdx.x * blockDim.x + threadIdx.x;
    if (i < E) {
        int dn = dst[i];
        int slot = atomicAdd(&g_deg[dn], 1);
        if (slot < ELLW) g_ell[dn * ELLW + slot] = src[i];
    }
    if (i < N) {
        if (i == 0 || batch[i - 1] != batch[i]) atomicMin(&g_gstart[batch[i]], i);
    }
}

// ============ launch 2: lin0 (+ gstart monotone fix in block 0) ============
__global__ void k_lin0(const float* __restrict__ x, const float* __restrict__ w,
                       const float* __restrict__ b, float* __restrict__ feat, int N, int B) {
    __shared__ float sw[DIM * 33];
    __shared__ float sb[DIM];
    __shared__ float sx[16 * FIN];
    int t = threadIdx.x;
    if (blockIdx.x == 0 && t == 0) {
        g_gstart[B] = N;
        for (int bb = B - 1; bb >= 0; bb--)
            if (g_gstart[bb] > g_gstart[bb + 1]) g_gstart[bb] = g_gstart[bb + 1];
    }
    for (int i = t; i < DIM * FIN; i += 256) sw[(i >> 5) * 33 + (i & 31)] = w[i];
    if (t < DIM) sb[t] = b[t];
    __syncthreads();
    int d = t & 63, tq = t >> 6;
    for (int tile = blockIdx.x * 16; tile < N; tile += gridDim.x * 16) {
        for (int i = t; i < 16 * FIN; i += 256) {
            int n = tile + (i >> 5);
            sx[i] = (n < N) ? x[n * FIN + (i & 31)] : 0.0f;
        }
        __syncthreads();
#pragma unroll
        for (int k = 0; k < 4; k++) {
            int loc = tq * 4 + k;
            int n = tile + loc;
            if (n < N) {
                float acc = sb[d];
                const float* xr = &sx[loc * FIN];
#pragma unroll
                for (int f = 0; f < FIN; f++) acc += xr[f] * sw[d * 33 + f];
                feat[n * DIM + d] = fmaxf(acc, 0.0f);
            }
        }
        __syncthreads();
    }
}

// ============ fused gather + NNConv + GRU: FFMA2, 128-node tiles, pack-amortized ============
// smem (floats)
#define OFF_WA 0                               // [64 k][WAST] EW k-major scalar
#define OFF_WG (64 * WAST)                     // 4352: [64 k][WGST]
#define OFF_S  (OFF_WG + 64 * WGST)            // 29184: [64 k][AST2]
#define OFF_H  (OFF_S + 64 * AST2)             // 37632
#define OFF_M  (OFF_H + 64 * AST2)             // 46080
#define OFF_CB (OFF_M + 64 * AST2)             // 54528
#define OFF_B4 (OFF_CB + 64)                   // 54592
#define SMEM_ITER_FLOATS (OFF_B4 + 256)        // 54848 floats = 214.25 KB

__global__ void __launch_bounds__(512, 1)
k_iter(const float* __restrict__ fin, float* __restrict__ fout,
       const float* __restrict__ wih, const float* __restrict__ whh,
       const float* __restrict__ bih, const float* __restrict__ bhh,
       const float* __restrict__ convb, int N, int ci) {
    extern __shared__ float sm[];
    float* sWa = sm + OFF_WA;
    float* sWG = sm + OFF_WG;
    float* sS  = sm + OFF_S;
    float* sH  = sm + OFF_H;
    float* sM  = sm + OFF_M;
    float* sCb = sm + OFF_CB;
    float* sB4 = sm + OFF_B4;
    __shared__ int s_tile;

    int t = threadIdx.x;
    for (int i = t; i < DIM * DIM; i += 512) {
        int k = i >> 6, d = i & 63;
        sWa[k * WAST + d] = g_ew[i];
    }
    // gate weights: [k][grp*24 + pass*12 + g*4 + dd]
    for (int i = t; i < 3 * DIM * DIM; i += 512) {
        int r = i >> 6, k = i & 63;
        int g = r >> 6, d = r & 63;
        int grp = d >> 2, dd = d & 3;
        sWG[k * WGST + grp * 24 + g * 4 + dd]      = wih[i];
        sWG[k * WGST + grp * 24 + 12 + g * 4 + dd] = whh[i];
    }
    if (t < 64) {
        sCb[t] = convb[t];
        sB4[t]       = bih[t] + bhh[t];
        sB4[64 + t]  = bih[64 + t] + bhh[64 + t];
        sB4[128 + t] = bih[128 + t];
        sB4[192 + t] = bhh[128 + t];
    }
    if (t == 0) s_tile = atomicAdd(&g_ctr[ci], 1) * TILE;
    __syncthreads();

    int w = t >> 5, ln = t & 31;          // warp w = dims 4w..4w+3; lane = node-pairs 2ln, 64+2ln
    int col = t & 63, q16 = (t >> 6) * 16;
    int d0 = 4 * w;

    int tile = s_tile;
    while (tile < N) {
        // ---- gather: 16 nodes per thread, staged in 4-node chunks
#pragma unroll
        for (int jj = 0; jj < 16; jj += 4) {
            float sv[4], hv[4];
#pragma unroll
            for (int j = 0; j < 4; j++) {
                int n = tile + q16 + jj + j;
                float s = 0.0f, h = 0.0f;
                if (n < N) {
                    h = fin[n * DIM + col];
                    int dgc = g_deg[n]; if (dgc > ELLW) dgc = ELLW;
                    const int* er = &g_ell[n * ELLW];
                    for (int e = 0; e < dgc; e++) s += fin[er[e] * DIM + col];
                    s *= (dgc > 0) ? __fdividef(1.0f, (float)dgc) : 0.0f;
                }
                sv[j] = s; hv[j] = h;
            }
            *(float4*)&sS[col * AST2 + q16 + jj] = make_float4(sv[0], sv[1], sv[2], sv[3]);
            *(float4*)&sH[col * AST2 + q16 + jj] = make_float4(hv[0], hv[1], hv[2], hv[3]);
        }
        if (t == 0) s_tile = atomicAdd(&g_ctr[ci], 1) * TILE;
        __syncthreads();   // B1: publishes gather + s_tile
        int nxt = s_tile;

        // ---- stage A: m = relu(s @ EW + cb); warp = 4 dims x 128 nodes, lane = 2 node-pairs
        {
            ull a[4][2] = {{0,0},{0,0},{0,0},{0,0}};
            const float* Sp = &sS[2 * ln];
            const float* Wp = &sWa[d0];
#pragma unroll 4
            for (int k = 0; k < 64; k++) {
                ull sa = *(const ull*)&Sp[k * AST2];
                ull sb = *(const ull*)&Sp[k * AST2 + 64];
                float4 w4 = *(const float4*)&Wp[k * WAST];
                const float* pw = (const float*)&w4;
#pragma unroll
                for (int dd = 0; dd < 4; dd++) {
                    ull wp = pack2(pw[dd]);
                    a[dd][0] = ffma2(sa, wp, a[dd][0]);
                    a[dd][1] = ffma2(sb, wp, a[dd][1]);
                }
            }
#pragma unroll
            for (int dd = 0; dd < 4; dd++) {
                float cb = sCb[d0 + dd];
                float2 u0 = unpack2(a[dd][0]);
                float2 u1 = unpack2(a[dd][1]);
                *(float2*)&sM[(d0 + dd) * AST2 + 2 * ln] =
                    make_float2(fmaxf(u0.x + cb, 0.0f), fmaxf(u0.y + cb, 0.0f));
                *(float2*)&sM[(d0 + dd) * AST2 + 64 + 2 * ln] =
                    make_float2(fmaxf(u1.x + cb, 0.0f), fmaxf(u1.y + cb, 0.0f));
            }
        }
        __syncthreads();   // B2

        // ---- gates: warp = 4 dims x 128 nodes; pass1 input, pass2 folds hidden
        {
            ull ir[4][2] = {{0,0},{0,0},{0,0},{0,0}};
            ull iz[4][2] = {{0,0},{0,0},{0,0},{0,0}};
            ull inn[4][2] = {{0,0},{0,0},{0,0},{0,0}};
            ull hn[4][2] = {{0,0},{0,0},{0,0},{0,0}};
            const float* Wg = &sWG[24 * w];
            const float* Mp = &sM[2 * ln];
            const float* Hp = &sH[2 * ln];
            // pass 1: gi = m @ Wih^T
#pragma unroll 4
            for (int k = 0; k < 64; k++) {
                ull ma = *(const ull*)&Mp[k * AST2];
                ull mb = *(const ull*)&Mp[k * AST2 + 64];
                float4 wr4 = *(const float4*)&Wg[k * WGST];
                float4 wz4 = *(const float4*)&Wg[k * WGST + 4];
                float4 wn4 = *(const float4*)&Wg[k * WGST + 8];
                const float* pr = (const float*)&wr4;
                const float* pz = (const float*)&wz4;
                const float* pn = (const float*)&wn4;
#pragma unroll
                for (int dd = 0; dd < 4; dd++) {
                    ull wr = pack2(pr[dd]);
                    ir[dd][0] = ffma2(ma, wr, ir[dd][0]);
                    ir[dd][1] = ffma2(mb, wr, ir[dd][1]);
                    ull wz = pack2(pz[dd]);
                    iz[dd][0] = ffma2(ma, wz, iz[dd][0]);
                    iz[dd][1] = ffma2(mb, wz, iz[dd][1]);
                    ull wn = pack2(pn[dd]);
                    inn[dd][0] = ffma2(ma, wn, inn[dd][0]);
                    inn[dd][1] = ffma2(mb, wn, inn[dd][1]);
                }
            }
            // pass 2: gh = h @ Whh^T; fold r,z into ir,iz; hn separate
#pragma unroll 4
            for (int k = 0; k < 64; k++) {
                ull ha = *(const ull*)&Hp[k * AST2];
                ull hb = *(const ull*)&Hp[k * AST2 + 64];
                float4 vr4 = *(const float4*)&Wg[k * WGST + 12];
                float4 vz4 = *(const float4*)&Wg[k * WGST + 16];
                float4 vn4 = *(const float4*)&Wg[k * WGST + 20];
                const float* qr = (const float*)&vr4;
                const float* qz = (const float*)&vz4;
                const float* qn = (const float*)&vn4;
#pragma unroll
                for (int dd = 0; dd < 4; dd++) {
                    ull vr = pack2(qr[dd]);
                    ir[dd][0] = ffma2(ha, vr, ir[dd][0]);
                    ir[dd][1] = ffma2(hb, vr, ir[dd][1]);
                    ull vz = pack2(qz[dd]);
                    iz[dd][0] = ffma2(ha, vz, iz[dd][0]);
                    iz[dd][1] = ffma2(hb, vz, iz[dd][1]);
                    ull vn = pack2(qn[dd]);
                    hn[dd][0] = ffma2(ha, vn, hn[dd][0]);
                    hn[dd][1] = ffma2(hb, vn, hn[dd][1]);
                }
            }
            // epilogue: 4 dims x 4 nodes per lane
            float o[2][2][4];   // [pair][node-in-pair][dim]
#pragma unroll
            for (int dd = 0; dd < 4; dd++) {
                int d = d0 + dd;
                float bR = sB4[d], bZ = sB4[64 + d], bNi = sB4[128 + d], bNh = sB4[192 + d];
#pragma unroll
                for (int p = 0; p < 2; p++) {
                    float2 R  = unpack2(ir[dd][p]);
                    float2 Z  = unpack2(iz[dd][p]);
                    float2 I  = unpack2(inn[dd][p]);
                    float2 Hn = unpack2(hn[dd][p]);
                    float2 h0 = *(const float2*)&sH[d * AST2 + p * 64 + 2 * ln];
                    float r0 = fsig(R.x + bR), r1 = fsig(R.y + bR);
                    float z0 = fsig(Z.x + bZ), z1 = fsig(Z.y + bZ);
                    float g0 = ftanh(I.x + bNi + r0 * (Hn.x + bNh));
                    float g1 = ftanh(I.y + bNi + r1 * (Hn.y + bNh));
                    o[p][0][dd] = (1.0f - z0) * g0 + z0 * h0.x;
                    o[p][1][dd] = (1.0f - z1) * g1 + z1 * h0.y;
                }
            }
#pragma unroll
            for (int p = 0; p < 2; p++) {
#pragma unroll
                for (int c = 0; c < 2; c++) {
                    int n = tile + p * 64 + 2 * ln + c;
                    if (n < N)
                        *(float4*)&fout[n * DIM + d0] =
                            make_float4(o[p][c][0], o[p][c][1], o[p][c][2], o[p][c][3]);
                }
            }
        }
        __syncthreads();   // B3: protect single-buffered S/H/M before next gather
        tile = nxt;
    }
}

// ============ fused Set2Set with smem feature cache ============
#define S2_F 0
#define S2_E (S2_F + CAP * FS)
#define S2_RED (S2_E + CAP)
#define S2_GATE (S2_RED + 256)
#define S2_Q (S2_GATE + 256)
#define S2_HL (S2_Q + 128)
#define S2_CL (S2_HL + 64)
#define SMEM_S2S_FLOATS (S2_CL + 64)

__global__ void __launch_bounds__(256, 1)
k_set2set(const float* __restrict__ feat,
          const float* __restrict__ wih, const float* __restrict__ whh,
          const float* __restrict__ bih, const float* __restrict__ bhh,
          float* __restrict__ out) {
    extern __shared__ float sm[];
    float* sF = sm + S2_F;
    float* sE = sm + S2_E;
    float* sRed = sm + S2_RED;
    float* sGate = sm + S2_GATE;
    float* sQ = sm + S2_Q;
    float* sHl = sm + S2_HL;
    float* sCl = sm + S2_CL;

    int b = blockIdx.x, t = threadIdx.x;
    int s0 = g_gstart[b], s1 = g_gstart[b + 1], cnt = s1 - s0;
    int cc = (cnt < CAP) ? cnt : CAP;
    for (int i = t; i < cc * DIM; i += 256) {
        int j = i >> 6, d = i & 63;
        sF[j * FS + d] = feat[(s0 + j) * DIM + d];
    }
    if (t < 128) sQ[t] = 0.0f;
    if (t < 64) { sHl[t] = 0.0f; sCl[t] = 0.0f; }
    __syncthreads();

    for (int step = 0; step < 3; step++) {
        {
            float acc = bih[t] + bhh[t];
            const float* wr = &wih[t * 2 * DIM];
#pragma unroll
            for (int j = 0; j < 2 * DIM; j += 4) {
                float4 w = *(const float4*)&wr[j];
                float4 q = *(const float4*)&sQ[j];
                acc += w.x * q.x + w.y * q.y + w.z * q.z + w.w * q.w;
            }
            const float* vr = &whh[t * DIM];
#pragma unroll
            for (int j = 0; j < DIM; j += 4) {
                float4 w = *(const float4*)&vr[j];
                float4 h = *(const float4*)&sHl[j];
                acc += w.x * h.x + w.y * h.y + w.z * h.z + w.w * h.w;
            }
            sGate[t] = acc;
        }
        __syncthreads();
        if (t < 64) {
            float ig = fsig(sGate[t]);
            float fg = fsig(sGate[64 + t]);
            float gg = ftanh(sGate[128 + t]);
            float og = fsig(sGate[192 + t]);
            float c = fg * sCl[t] + ig * gg;
            sCl[t] = c;
            sHl[t] = og * ftanh(c);
        }
        __syncthreads();

        float mx = -1e30f;
        for (int j = t; j < cnt; j += 256) {
            float v = 0.0f;
            if (j < CAP) {
                const float* fr = &sF[j * FS];
#pragma unroll 8
                for (int dd = 0; dd < DIM; dd++) v += fr[dd] * sHl[dd];
                sE[j] = v;
            } else {
                const float* fr = &feat[(s0 + j) * DIM];
                for (int dd = 0; dd < DIM; dd++) v += fr[dd] * sHl[dd];
                g_e[s0 + j] = v;
            }
            mx = fmaxf(mx, v);
        }
        sRed[t] = mx;
        __syncthreads();
        for (int off = 128; off > 0; off >>= 1) {
            if (t < off) sRed[t] = fmaxf(sRed[t], sRed[t + off]);
            __syncthreads();
        }
        float emax = (cnt > 0) ? sRed[0] : 0.0f;
        __syncthreads();

        float sme = 0.0f;
        for (int j = t; j < cnt; j += 256) {
            float e = (j < CAP) ? sE[j] : g_e[s0 + j];
            sme += __expf(e - emax);
        }
        sRed[t] = sme;
        __syncthreads();
        for (int off = 128; off > 0; off >>= 1) {
            if (t < off) sRed[t] += sRed[t + off];
            __syncthreads();
        }
        float scale = __fdividef(1.0f, sRed[0] + 1e-16f);
        __syncthreads();
        for (int j = t; j < cnt; j += 256) {
            if (j < CAP) sE[j] = __expf(sE[j] - emax) * scale;
            else g_e[s0 + j] = __expf(g_e[s0 + j] - emax) * scale;
        }
        __syncthreads();

        {
            int d = t & 63, q = t >> 6;
            float acc = 0.0f;
            for (int j = q; j < cnt; j += 4) {
                float a = (j < CAP) ? sE[j] : g_e[s0 + j];
                float fv = (j < CAP) ? sF[j * FS + d] : feat[(s0 + j) * DIM + d];
                acc += a * fv;
            }
            sRed[t] = acc;
        }
        __syncthreads();
        if (t < 64) {
            float r = sRed[t] + sRed[64 + t] + sRed[128 + t] + sRed[192 + t];
            if (step == 2) {
                out[b * 2 * DIM + t] = sHl[t];
                out[b * 2 * DIM + DIM + t] = r;
            } else {
                sQ[t] = sHl[t];
                sQ[DIM + t] = r;
            }
        }
        __syncthreads();
    }
}

// ---------------- launch ----------------
extern "C" void kernel_launch(void* const* d_in, const int* in_sizes, int n_in,
                              void* d_out, int out_size) {
    const float* x        = (const float*)d_in[0];
    const int*   ei       = (const int*)d_in[1];
    const int*   batch    = (const int*)d_in[2];
    const float* lin0_w   = (const float*)d_in[3];
    const float* lin0_b   = (const float*)d_in[4];
    const float* nn1_w    = (const float*)d_in[5];
    const float* nn1_b    = (const float*)d_in[6];
    const float* nn2_w    = (const float*)d_in[7];
    const float* nn2_b    = (const float*)d_in[8];
    const float* conv_b   = (const float*)d_in[9];
    const float* gru_w_ih = (const float*)d_in[10];
    const float* gru_w_hh = (const float*)d_in[11];
    const float* gru_b_ih = (const float*)d_in[12];
    const float* gru_b_hh = (const float*)d_in[13];
    const float* lstm_w_ih = (const float*)d_in[14];
    const float* lstm_w_hh = (const float*)d_in[15];
    const float* lstm_b_ih = (const float*)d_in[16];
    const float* lstm_b_hh = (const float*)d_in[17];

    int N = in_sizes[2];
    int E = in_sizes[1] / 2;
    int B = (out_size - N * DIM) / (2 * DIM);

    float* out  = (float*)d_out;
    float* feat = out + B * 2 * DIM;

    float* feat2 = nullptr;
    cudaGetSymbolAddress((void**)&feat2, g_feat2);

    const int* src = ei;
    const int* dst = ei + E;

    const size_t smem_iter = SMEM_ITER_FLOATS * sizeof(float);
    const size_t smem_s2s  = SMEM_S2S_FLOATS * sizeof(float);
    cudaFuncSetAttribute(k_iter, cudaFuncAttributeMaxDynamicSharedMemorySize, (int)smem_iter);
    cudaFuncSetAttribute(k_set2set, cudaFuncAttributeMaxDynamicSharedMemorySize, (int)smem_s2s);

    int mx1 = (N > DIM * DIM ? N : DIM * DIM);
    int mx2 = (E > N ? E : N);

    // 0: EW + zero deg + gstart init + steal-counter reset
    k_init<<<(mx1 + 1023) / 1024, 1024>>>(nn1_w, nn1_b, nn2_w, nn2_b, N, B);
    // 1: ELL adjacency insert + graph-start marks
    k_count<<<(mx2 + 1023) / 1024, 1024>>>(src, dst, batch, E, N);
    // 2: lin0 (+ gstart fix)
    k_lin0<<<148, 256>>>(x, lin0_w, lin0_b, feat2, N, B);

    // 3..5: fused gather + NNConv + GRU, 128-node tiles, work stealing
    k_iter<<<148, 512, smem_iter>>>(feat2, feat, gru_w_ih, gru_w_hh, gru_b_ih, gru_b_hh, conv_b, N, 0);
    k_iter<<<148, 512, smem_iter>>>(feat, feat2, gru_w_ih, gru_w_hh, gru_b_ih, gru_b_hh, conv_b, N, 1);
    k_iter<<<148, 512, smem_iter>>>(feat2, feat, gru_w_ih, gru_w_hh, gru_b_ih, gru_b_hh, conv_b, N, 2);

    // 6: fused Set2Set
    k_set2set<<<B, 256, smem_s2s>>>(feat, lstm_w_ih, lstm_w_hh, lstm_b_ih, lstm_b_hh, out);
}

// round 16
// speedup vs baseline: 1.0384x; 1.0162x over previous
#include <cuda_runtime.h>
#include <math.h>

#define DIM 64
#define FIN 32
#define MAXN 50048
#define MAXE 60032
#define MAXB 256
#define ELLW 16
#define CAP 320
#define FS 65

#define TILE 128
#define AST2 132    // activation stride (dim-major [64][128 nodes + pad])
#define WAST 68     // stage A weight stride
#define WGST 388    // gate weight stride: 32 dpairs * 12 + pad

typedef unsigned long long ull;

// ---------------- device scratch ----------------
__device__ float g_ew[DIM * DIM];
__device__ float g_feat2[MAXN * DIM];
__device__ int   g_deg[MAXN];
__device__ int   g_ell[MAXN * ELLW];
__device__ float g_e[MAXN];
__device__ int   g_gstart[MAXB + 1];
__device__ int   g_ctr[4];

__device__ __forceinline__ float fsig(float x) {
    return __fdividef(1.0f, 1.0f + __expf(-x));
}
__device__ __forceinline__ float ftanh(float x) {
    float e = __expf(2.0f * x);
    return __fdividef(e - 1.0f, e + 1.0f);
}
__device__ __forceinline__ ull ffma2(ull a, ull b, ull c) {
    ull d;
    asm("fma.rn.f32x2 %0, %1, %2, %3;" : "=l"(d) : "l"(a), "l"(b), "l"(c));
    return d;
}
__device__ __forceinline__ ull pack2(float x) {
    ull r;
    asm("mov.b64 %0, {%1, %1};" : "=l"(r) : "r"(__float_as_uint(x)));
    return r;
}
__device__ __forceinline__ float2 unpack2(ull v) {
    float2 f;
    asm("mov.b64 {%0, %1}, %2;" : "=f"(f.x), "=f"(f.y) : "l"(v));
    return f;
}

// ============ launch 0: EW + zero deg + init gstart + zero steal counters ============
__global__ void k_init(const float* __restrict__ nn1_w, const float* __restrict__ nn1_b,
                       const float* __restrict__ nn2_w, const float* __restrict__ nn2_b,
                       int N, int B) {
    int i = blockIdx.x * blockDim.x + threadIdx.x;
    if (i < DIM * DIM) {
        float acc = nn2_b[i];
        const float* row = &nn2_w[i * DIM];
#pragma unroll 8
        for (int dd = 0; dd < DIM; dd++)
            acc += fmaxf(nn1_w[dd] + nn1_b[dd], 0.0f) * row[dd];
        g_ew[i] = acc;
    }
    if (i < N) g_deg[i] = 0;
    if (i <= B) g_gstart[i] = N;
    if (i < 4) g_ctr[i] = 0;
}

// ============ launch 1: ELL insert + mark graph starts ============
__global__ void k_count(const int* __restrict__ src, const int* __restrict__ dst,
                        const int* __restrict__ batch, int E, int N) {
    int i = blockIdx.x * blockDim.x + threadIdx.x;
    if (i < E) {
        int dn = dst[i];
        int slot = atomicAdd(&g_deg[dn], 1);
        if (slot < ELLW) g_ell[dn * ELLW + slot] = src[i];
    }
    if (i < N) {
        if (i == 0 || batch[i - 1] != batch[i]) atomicMin(&g_gstart[batch[i]], i);
    }
}

// ============ launch 2: lin0 (+ gstart monotone fix in block 0) ============
__global__ void k_lin0(const float* __restrict__ x, const float* __restrict__ w,
                       const float* __restrict__ b, float* __restrict__ feat, int N, int B) {
    __shared__ float sw[DIM * 33];
    __shared__ float sb[DIM];
    __shared__ float sx[16 * FIN];
    int t = threadIdx.x;
    if (blockIdx.x == 0 && t == 0) {
        g_gstart[B] = N;
        for (int bb = B - 1; bb >= 0; bb--)
            if (g_gstart[bb] > g_gstart[bb + 1]) g_gstart[bb] = g_gstart[bb + 1];
    }
    for (int i = t; i < DIM * FIN; i += 256) sw[(i >> 5) * 33 + (i & 31)] = w[i];
    if (t < DIM) sb[t] = b[t];
    __syncthreads();
    int d = t & 63, tq = t >> 6;
    for (int tile = blockIdx.x * 16; tile < N; tile += gridDim.x * 16) {
        for (int i = t; i < 16 * FIN; i += 256) {
            int n = tile + (i >> 5);
            sx[i] = (n < N) ? x[n * FIN + (i & 31)] : 0.0f;
        }
        __syncthreads();
#pragma unroll
        for (int k = 0; k < 4; k++) {
            int loc = tq * 4 + k;
            int n = tile + loc;
            if (n < N) {
                float acc = sb[d];
                const float* xr = &sx[loc * FIN];
#pragma unroll
                for (int f = 0; f < FIN; f++) acc += xr[f] * sw[d * 33 + f];
                feat[n * DIM + d] = fmaxf(acc, 0.0f);
            }
        }
        __syncthreads();
    }
}

// ============ fused gather + NNConv + GRU: FFMA2, 1024 threads, 2 dims/warp ============
// smem (floats)
#define OFF_WA 0                               // [64 k][WAST] EW k-major scalar
#define OFF_WG (64 * WAST)                     // 4352: [64 k][WGST]: dp*12 + pass*6 + g*2 + dd
#define OFF_S  (OFF_WG + 64 * WGST)            // 29184: [64 k][AST2]
#define OFF_H  (OFF_S + 64 * AST2)             // 37632
#define OFF_M  (OFF_H + 64 * AST2)             // 46080
#define OFF_CB (OFF_M + 64 * AST2)             // 54528
#define OFF_B4 (OFF_CB + 64)                   // 54592
#define SMEM_ITER_FLOATS (OFF_B4 + 256)        // 54848 floats = 214.25 KB

__global__ void __launch_bounds__(1024, 1)
k_iter(const float* __restrict__ fin, float* __restrict__ fout,
       const float* __restrict__ wih, const float* __restrict__ whh,
       const float* __restrict__ bih, const float* __restrict__ bhh,
       const float* __restrict__ convb, int N, int ci) {
    extern __shared__ float sm[];
    float* sWa = sm + OFF_WA;
    float* sWG = sm + OFF_WG;
    float* sS  = sm + OFF_S;
    float* sH  = sm + OFF_H;
    float* sM  = sm + OFF_M;
    float* sCb = sm + OFF_CB;
    float* sB4 = sm + OFF_B4;
    __shared__ int s_tile;

    int t = threadIdx.x;
    for (int i = t; i < DIM * DIM; i += 1024) {
        int k = i >> 6, d = i & 63;
        sWa[k * WAST + d] = g_ew[i];
    }
    // gate weights: [k][dp*12 + pass*6 + g*2 + dd]; dp = d>>1, dd = d&1
    for (int i = t; i < 3 * DIM * DIM; i += 1024) {
        int r = i >> 6, k = i & 63;
        int g = r >> 6, d = r & 63;
        int dp = d >> 1, dd = d & 1;
        sWG[k * WGST + dp * 12 + g * 2 + dd]     = wih[i];
        sWG[k * WGST + dp * 12 + 6 + g * 2 + dd] = whh[i];
    }
    if (t < 64) {
        sCb[t] = convb[t];
        sB4[t]       = bih[t] + bhh[t];
        sB4[64 + t]  = bih[64 + t] + bhh[64 + t];
        sB4[128 + t] = bih[128 + t];
        sB4[192 + t] = bhh[128 + t];
    }
    if (t == 0) s_tile = atomicAdd(&g_ctr[ci], 1) * TILE;
    __syncthreads();

    int w = t >> 5, ln = t & 31;          // 32 warps; warp w = dims 2w,2w+1; lane = pairs 2ln, 64+2ln
    int col = t & 63, q8 = (t >> 6) * 8;  // gather: 16 groups x 8 nodes
    int d0 = 2 * w;

    int tile = s_tile;
    while (tile < N) {
        // ---- gather: 8 nodes per thread, staged in 4-node chunks
#pragma unroll
        for (int jj = 0; jj < 8; jj += 4) {
            float sv[4], hv[4];
#pragma unroll
            for (int j = 0; j < 4; j++) {
                int n = tile + q8 + jj + j;
                float s = 0.0f, h = 0.0f;
                if (n < N) {
                    h = fin[n * DIM + col];
                    int dgc = g_deg[n]; if (dgc > ELLW) dgc = ELLW;
                    const int* er = &g_ell[n * ELLW];
                    for (int e = 0; e < dgc; e++) s += fin[er[e] * DIM + col];
                    s *= (dgc > 0) ? __fdividef(1.0f, (float)dgc) : 0.0f;
                }
                sv[j] = s; hv[j] = h;
            }
            *(float4*)&sS[col * AST2 + q8 + jj] = make_float4(sv[0], sv[1], sv[2], sv[3]);
            *(float4*)&sH[col * AST2 + q8 + jj] = make_float4(hv[0], hv[1], hv[2], hv[3]);
        }
        if (t == 0) s_tile = atomicAdd(&g_ctr[ci], 1) * TILE;
        __syncthreads();   // B1
        int nxt = s_tile;

        // ---- stage A: m = relu(s @ EW + cb); warp = 2 dims x 128 nodes
        {
            ull a[2][2] = {{0,0},{0,0}};
            const float* Sp = &sS[2 * ln];
            const float* Wp = &sWa[d0];
#pragma unroll 4
            for (int k = 0; k < 64; k++) {
                ull sa = *(const ull*)&Sp[k * AST2];
                ull sb = *(const ull*)&Sp[k * AST2 + 64];
                float2 w2 = *(const float2*)&Wp[k * WAST];
                ull p0 = pack2(w2.x);
                a[0][0] = ffma2(sa, p0, a[0][0]);
                a[0][1] = ffma2(sb, p0, a[0][1]);
                ull p1 = pack2(w2.y);
                a[1][0] = ffma2(sa, p1, a[1][0]);
                a[1][1] = ffma2(sb, p1, a[1][1]);
            }
#pragma unroll
            for (int dd = 0; dd < 2; dd++) {
                float cb = sCb[d0 + dd];
                float2 u0 = unpack2(a[dd][0]);
                float2 u1 = unpack2(a[dd][1]);
                *(float2*)&sM[(d0 + dd) * AST2 + 2 * ln] =
                    make_float2(fmaxf(u0.x + cb, 0.0f), fmaxf(u0.y + cb, 0.0f));
                *(float2*)&sM[(d0 + dd) * AST2 + 64 + 2 * ln] =
                    make_float2(fmaxf(u1.x + cb, 0.0f), fmaxf(u1.y + cb, 0.0f));
            }
        }
        __syncthreads();   // B2

        // ---- gates: warp = 2 dims x 128 nodes; pass1 input, pass2 folds hidden
        {
            ull ir[2][2] = {{0,0},{0,0}};
            ull iz[2][2] = {{0,0},{0,0}};
            ull inn[2][2] = {{0,0},{0,0}};
            ull hn[2][2] = {{0,0},{0,0}};
            const float* Wg = &sWG[12 * w];
            const float* Mp = &sM[2 * ln];
            const float* Hp = &sH[2 * ln];
            // pass 1: gi = m @ Wih^T
#pragma unroll 4
            for (int k = 0; k < 64; k++) {
                ull ma = *(const ull*)&Mp[k * AST2];
                ull mb = *(const ull*)&Mp[k * AST2 + 64];
                float2 wr = *(const float2*)&Wg[k * WGST];
                float2 wz = *(const float2*)&Wg[k * WGST + 2];
                float2 wn = *(const float2*)&Wg[k * WGST + 4];
                ull p;
                p = pack2(wr.x); ir[0][0] = ffma2(ma, p, ir[0][0]); ir[0][1] = ffma2(mb, p, ir[0][1]);
                p = pack2(wr.y); ir[1][0] = ffma2(ma, p, ir[1][0]); ir[1][1] = ffma2(mb, p, ir[1][1]);
                p = pack2(wz.x); iz[0][0] = ffma2(ma, p, iz[0][0]); iz[0][1] = ffma2(mb, p, iz[0][1]);
                p = pack2(wz.y); iz[1][0] = ffma2(ma, p, iz[1][0]); iz[1][1] = ffma2(mb, p, iz[1][1]);
                p = pack2(wn.x); inn[0][0] = ffma2(ma, p, inn[0][0]); inn[0][1] = ffma2(mb, p, inn[0][1]);
                p = pack2(wn.y); inn[1][0] = ffma2(ma, p, inn[1][0]); inn[1][1] = ffma2(mb, p, inn[1][1]);
            }
            // pass 2: gh = h @ Whh^T; fold r,z; hn separate
#pragma unroll 4
            for (int k = 0; k < 64; k++) {
                ull ha = *(const ull*)&Hp[k * AST2];
                ull hb = *(const ull*)&Hp[k * AST2 + 64];
                float2 vr = *(const float2*)&Wg[k * WGST + 6];
                float2 vz = *(const float2*)&Wg[k * WGST + 8];
                float2 vn = *(const float2*)&Wg[k * WGST + 10];
                ull p;
                p = pack2(vr.x); ir[0][0] = ffma2(ha, p, ir[0][0]); ir[0][1] = ffma2(hb, p, ir[0][1]);
                p = pack2(vr.y); ir[1][0] = ffma2(ha, p, ir[1][0]); ir[1][1] = ffma2(hb, p, ir[1][1]);
                p = pack2(vz.x); iz[0][0] = ffma2(ha, p, iz[0][0]); iz[0][1] = ffma2(hb, p, iz[0][1]);
                p = pack2(vz.y); iz[1][0] = ffma2(ha, p, iz[1][0]); iz[1][1] = ffma2(hb, p, iz[1][1]);
                p = pack2(vn.x); hn[0][0] = ffma2(ha, p, hn[0][0]); hn[0][1] = ffma2(hb, p, hn[0][1]);
                p = pack2(vn.y); hn[1][0] = ffma2(ha, p, hn[1][0]); hn[1][1] = ffma2(hb, p, hn[1][1]);
            }
            // epilogue: 2 dims x 4 nodes per lane
#pragma unroll
            for (int p2 = 0; p2 < 2; p2++) {
                float o[2][2];   // [node-in-pair][dim]
#pragma unroll
                for (int dd = 0; dd < 2; dd++) {
                    int d = d0 + dd;
                    float bR = sB4[d], bZ = sB4[64 + d], bNi = sB4[128 + d], bNh = sB4[192 + d];
                    float2 R  = unpack2(ir[dd][p2]);
                    float2 Z  = unpack2(iz[dd][p2]);
                    float2 I  = unpack2(inn[dd][p2]);
                    float2 Hn = unpack2(hn[dd][p2]);
                    float2 h0 = *(const float2*)&sH[d * AST2 + p2 * 64 + 2 * ln];
                    float r0 = fsig(R.x + bR), r1 = fsig(R.y + bR);
                    float z0 = fsig(Z.x + bZ), z1 = fsig(Z.y + bZ);
                    float g0 = ftanh(I.x + bNi + r0 * (Hn.x + bNh));
                    float g1 = ftanh(I.y + bNi + r1 * (Hn.y + bNh));
                    o[0][dd] = (1.0f - z0) * g0 + z0 * h0.x;
                    o[1][dd] = (1.0f - z1) * g1 + z1 * h0.y;
                }
#pragma unroll
                for (int c = 0; c < 2; c++) {
                    int n = tile + p2 * 64 + 2 * ln + c;
                    if (n < N)
                        *(float2*)&fout[n * DIM + d0] = make_float2(o[c][0], o[c][1]);
                }
            }
        }
        __syncthreads();   // B3
        tile = nxt;
    }
}

// ============ fused Set2Set with smem feature cache ============
#define S2_F 0
#define S2_E (S2_F + CAP * FS)
#define S2_RED (S2_E + CAP)
#define S2_GATE (S2_RED + 256)
#define S2_Q (S2_GATE + 256)
#define S2_HL (S2_Q + 128)
#define S2_CL (S2_HL + 64)
#define SMEM_S2S_FLOATS (S2_CL + 64)

__global__ void __launch_bounds__(256, 1)
k_set2set(const float* __restrict__ feat,
          const float* __restrict__ wih, const float* __restrict__ whh,
          const float* __restrict__ bih, const float* __restrict__ bhh,
          float* __restrict__ out) {
    extern __shared__ float sm[];
    float* sF = sm + S2_F;
    float* sE = sm + S2_E;
    float* sRed = sm + S2_RED;
    float* sGate = sm + S2_GATE;
    float* sQ = sm + S2_Q;
    float* sHl = sm + S2_HL;
    float* sCl = sm + S2_CL;

    int b = blockIdx.x, t = threadIdx.x;
    int s0 = g_gstart[b], s1 = g_gstart[b + 1], cnt = s1 - s0;
    int cc = (cnt < CAP) ? cnt : CAP;
    for (int i = t; i < cc * DIM; i += 256) {
        int j = i >> 6, d = i & 63;
        sF[j * FS + d] = feat[(s0 + j) * DIM + d];
    }
    if (t < 128) sQ[t] = 0.0f;
    if (t < 64) { sHl[t] = 0.0f; sCl[t] = 0.0f; }
    __syncthreads();

    for (int step = 0; step < 3; step++) {
        {
            float acc = bih[t] + bhh[t];
            const float* wr = &wih[t * 2 * DIM];
#pragma unroll
            for (int j = 0; j < 2 * DIM; j += 4) {
                float4 w = *(const float4*)&wr[j];
                float4 q = *(const float4*)&sQ[j];
                acc += w.x * q.x + w.y * q.y + w.z * q.z + w.w * q.w;
            }
            const float* vr = &whh[t * DIM];
#pragma unroll
            for (int j = 0; j < DIM; j += 4) {
                float4 w = *(const float4*)&vr[j];
                float4 h = *(const float4*)&sHl[j];
                acc += w.x * h.x + w.y * h.y + w.z * h.z + w.w * h.w;
            }
            sGate[t] = acc;
        }
        __syncthreads();
        if (t < 64) {
            float ig = fsig(sGate[t]);
            float fg = fsig(sGate[64 + t]);
            float gg = ftanh(sGate[128 + t]);
            float og = fsig(sGate[192 + t]);
            float c = fg * sCl[t] + ig * gg;
            sCl[t] = c;
            sHl[t] = og * ftanh(c);
        }
        __syncthreads();

        float mx = -1e30f;
        for (int j = t; j < cnt; j += 256) {
            float v = 0.0f;
            if (j < CAP) {
                const float* fr = &sF[j * FS];
#pragma unroll 8
                for (int dd = 0; dd < DIM; dd++) v += fr[dd] * sHl[dd];
                sE[j] = v;
            } else {
                const float* fr = &feat[(s0 + j) * DIM];
                for (int dd = 0; dd < DIM; dd++) v += fr[dd] * sHl[dd];
                g_e[s0 + j] = v;
            }
            mx = fmaxf(mx, v);
        }
        sRed[t] = mx;
        __syncthreads();
        for (int off = 128; off > 0; off >>= 1) {
            if (t < off) sRed[t] = fmaxf(sRed[t], sRed[t + off]);
            __syncthreads();
        }
        float emax = (cnt > 0) ? sRed[0] : 0.0f;
        __syncthreads();

        float sme = 0.0f;
        for (int j = t; j < cnt; j += 256) {
            float e = (j < CAP) ? sE[j] : g_e[s0 + j];
            sme += __expf(e - emax);
        }
        sRed[t] = sme;
        __syncthreads();
        for (int off = 128; off > 0; off >>= 1) {
            if (t < off) sRed[t] += sRed[t + off];
            __syncthreads();
        }
        float scale = __fdividef(1.0f, sRed[0] + 1e-16f);
        __syncthreads();
        for (int j = t; j < cnt; j += 256) {
            if (j < CAP) sE[j] = __expf(sE[j] - emax) * scale;
            else g_e[s0 + j] = __expf(g_e[s0 + j] - emax) * scale;
        }
        __syncthreads();

        {
            int d = t & 63, q = t >> 6;
            float acc = 0.0f;
            for (int j = q; j < cnt; j += 4) {
                float a = (j < CAP) ? sE[j] : g_e[s0 + j];
                float fv = (j < CAP) ? sF[j * FS + d] : feat[(s0 + j) * DIM + d];
                acc += a * fv;
            }
            sRed[t] = acc;
        }
        __syncthreads();
        if (t < 64) {
            float r = sRed[t] + sRed[64 + t] + sRed[128 + t] + sRed[192 + t];
            if (step == 2) {
                out[b * 2 * DIM + t] = sHl[t];
                out[b * 2 * DIM + DIM + t] = r;
            } else {
                sQ[t] = sHl[t];
                sQ[DIM + t] = r;
            }
        }
        __syncthreads();
    }
}

// ---------------- launch ----------------
extern "C" void kernel_launch(void* const* d_in, const int* in_sizes, int n_in,
                              void* d_out, int out_size) {
    const float* x        = (const float*)d_in[0];
    const int*   ei       = (const int*)d_in[1];
    const int*   batch    = (const int*)d_in[2];
    const float* lin0_w   = (const float*)d_in[3];
    const float* lin0_b   = (const float*)d_in[4];
    const float* nn1_w    = (const float*)d_in[5];
    const float* nn1_b    = (const float*)d_in[6];
    const float* nn2_w    = (const float*)d_in[7];
    const float* nn2_b    = (const float*)d_in[8];
    const float* conv_b   = (const float*)d_in[9];
    const float* gru_w_ih = (const float*)d_in[10];
    const float* gru_w_hh = (const float*)d_in[11];
    const float* gru_b_ih = (const float*)d_in[12];
    const float* gru_b_hh = (const float*)d_in[13];
    const float* lstm_w_ih = (const float*)d_in[14];
    const float* lstm_w_hh = (const float*)d_in[15];
    const float* lstm_b_ih = (const float*)d_in[16];
    const float* lstm_b_hh = (const float*)d_in[17];

    int N = in_sizes[2];
    int E = in_sizes[1] / 2;
    int B = (out_size - N * DIM) / (2 * DIM);

    float* out  = (float*)d_out;
    float* feat = out + B * 2 * DIM;

    float* feat2 = nullptr;
    cudaGetSymbolAddress((void**)&feat2, g_feat2);

    const int* src = ei;
    const int* dst = ei + E;

    const size_t smem_iter = SMEM_ITER_FLOATS * sizeof(float);
    const size_t smem_s2s  = SMEM_S2S_FLOATS * sizeof(float);
    cudaFuncSetAttribute(k_iter, cudaFuncAttributeMaxDynamicSharedMemorySize, (int)smem_iter);
    cudaFuncSetAttribute(k_set2set, cudaFuncAttributeMaxDynamicSharedMemorySize, (int)smem_s2s);

    int mx1 = (N > DIM * DIM ? N : DIM * DIM);
    int mx2 = (E > N ? E : N);

    // 0: EW + zero deg + gstart init + steal-counter reset
    k_init<<<(mx1 + 1023) / 1024, 1024>>>(nn1_w, nn1_b, nn2_w, nn2_b, N, B);
    // 1: ELL adjacency insert + graph-start marks
    k_count<<<(mx2 + 1023) / 1024, 1024>>>(src, dst, batch, E, N);
    // 2: lin0 (+ gstart fix)
    k_lin0<<<148, 256>>>(x, lin0_w, lin0_b, feat2, N, B);

    // 3..5: fused gather + NNConv + GRU, 1024 threads, work stealing
    k_iter<<<148, 1024, smem_iter>>>(feat2, feat, gru_w_ih, gru_w_hh, gru_b_ih, gru_b_hh, conv_b, N, 0);
    k_iter<<<148, 1024, smem_iter>>>(feat, feat2, gru_w_ih, gru_w_hh, gru_b_ih, gru_b_hh, conv_b, N, 1);
    k_iter<<<148, 1024, smem_iter>>>(feat2, feat, gru_w_ih, gru_w_hh, gru_b_ih, gru_b_hh, conv_b, N, 2);

    // 6: fused Set2Set
    k_set2set<<<B, 256, smem_s2s>>>(feat, lstm_w_ih, lstm_w_hh, lstm_b_ih, lstm_b_hh, out);
}